// round 3
// baseline (speedup 1.0000x reference)
#include <cuda_runtime.h>
#include <math.h>

// Problem constants
#define BB 32
#define SS 2048
#define HH 1024
#define MTOT (BB*SS)      // 65536 rows of the big GEMM
#define TM 128
#define TN 128
#define TK 16
#define NT (HH/TN)        // 8 o-tiles

// Device scratch (no allocations allowed)
__device__ float g_qc[BB*HH];          // query[b,o] + Wa_b[o] + Ua_b[o]
__device__ float g_part[NT][MTOT];     // per-o-tile partial energies (deterministic, no atomics)

// Accurate-enough tanh that does not depend on fast-math flags.
// |err| <~ 2e-6 absolute; clamp avoids exp overflow.
__device__ __forceinline__ float tanh_acc(float x) {
    float xc = fminf(fmaxf(x, -15.f), 15.f);
    float e = __expf(2.f * xc);
    return __fdividef(e - 1.f, e + 1.f);
}

// ---------------------------------------------------------------------------
// Kernel 1: qc[b,o] = sum_h dec[b,h]*Wa_w[o,h] + Wa_b[o] + Ua_b[o]
// One warp per (b,o). 32768 warps; trivial cost.
// ---------------------------------------------------------------------------
__global__ void qc_kernel(const float* __restrict__ dec,
                          const float* __restrict__ Wa_w,
                          const float* __restrict__ Wa_b,
                          const float* __restrict__ Ua_b) {
    int gw   = (blockIdx.x * blockDim.x + threadIdx.x) >> 5;
    int lane = threadIdx.x & 31;
    if (gw >= BB * HH) return;
    int b = gw >> 10;           // /HH
    int o = gw & (HH - 1);
    const float* dr = dec + b * HH;
    const float* wr = Wa_w + o * HH;
    float s = 0.f;
    #pragma unroll 8
    for (int h = lane; h < HH; h += 32) s = fmaf(dr[h], wr[h], s);
    #pragma unroll
    for (int off = 16; off; off >>= 1) s += __shfl_xor_sync(0xffffffffu, s, off);
    if (lane == 0) g_qc[gw] = s + Wa_b[o] + Ua_b[o];
}

// ---------------------------------------------------------------------------
// Kernel 2: fused energy GEMM.
// C[m,o] = enc[m,:]·Ua_w[o,:]  (both K-major), then per-row partial energy
//   part[m] (this o-tile) = sum_o Va[o]*tanh(C[m,o] + qc[b,o])
// Grid: (NT o-tiles, MTOT/TM row-tiles). 128x128x16 tile, 8x8 microtile,
// register-prefetch pipelining. No bounds checks needed (all dims divide).
// ---------------------------------------------------------------------------
__global__ __launch_bounds__(256, 2)
void energy_gemm(const float* __restrict__ A,     // enc  [MTOT, HH]
                 const float* __restrict__ Bm,    // Ua_w [HH(o), HH(k)]
                 const float* __restrict__ Va) {  // Va_w [HH]
    __shared__ float As[TK][TM + 4];
    __shared__ float Bs[TK][TN + 4];

    const int ot = blockIdx.x;
    const int m0 = blockIdx.y * TM;
    const int o0 = ot * TN;
    const int tid = threadIdx.x;
    const int tx = tid & 15;        // o-dim microtile index
    const int ty = tid >> 4;        // m-dim microtile index
    const int lr = tid >> 2;        // load row 0..63
    const int lc = (tid & 3) << 2;  // load k-offset 0,4,8,12

    const float* Ap = A  + (size_t)(m0 + lr) * HH + lc;
    const float* Bp = Bm + (size_t)(o0 + lr) * HH + lc;

    float4 pa0 = *(const float4*)(Ap);
    float4 pa1 = *(const float4*)(Ap + (size_t)64 * HH);
    float4 pb0 = *(const float4*)(Bp);
    float4 pb1 = *(const float4*)(Bp + (size_t)64 * HH);

    float acc[8][8];
    #pragma unroll
    for (int i = 0; i < 8; ++i)
        #pragma unroll
        for (int j = 0; j < 8; ++j) acc[i][j] = 0.f;

    for (int kt = 0; kt < HH / TK; ++kt) {
        // commit prefetched tiles (transposed: [k][m] / [k][o])
        As[lc+0][lr]    = pa0.x; As[lc+1][lr]    = pa0.y; As[lc+2][lr]    = pa0.z; As[lc+3][lr]    = pa0.w;
        As[lc+0][lr+64] = pa1.x; As[lc+1][lr+64] = pa1.y; As[lc+2][lr+64] = pa1.z; As[lc+3][lr+64] = pa1.w;
        Bs[lc+0][lr]    = pb0.x; Bs[lc+1][lr]    = pb0.y; Bs[lc+2][lr]    = pb0.z; Bs[lc+3][lr]    = pb0.w;
        Bs[lc+0][lr+64] = pb1.x; Bs[lc+1][lr+64] = pb1.y; Bs[lc+2][lr+64] = pb1.z; Bs[lc+3][lr+64] = pb1.w;
        __syncthreads();

        if (kt + 1 < HH / TK) {  // prefetch next K-panel while computing
            const float* Ap2 = Ap + (kt + 1) * TK;
            const float* Bp2 = Bp + (kt + 1) * TK;
            pa0 = *(const float4*)(Ap2);
            pa1 = *(const float4*)(Ap2 + (size_t)64 * HH);
            pb0 = *(const float4*)(Bp2);
            pb1 = *(const float4*)(Bp2 + (size_t)64 * HH);
        }

        #pragma unroll
        for (int k = 0; k < TK; ++k) {
            float a[8], bb[8];
            *(float4*)&a[0]  = *(const float4*)&As[k][ty * 8];
            *(float4*)&a[4]  = *(const float4*)&As[k][ty * 8 + 4];
            *(float4*)&bb[0] = *(const float4*)&Bs[k][tx * 8];
            *(float4*)&bb[4] = *(const float4*)&Bs[k][tx * 8 + 4];
            #pragma unroll
            for (int i = 0; i < 8; ++i)
                #pragma unroll
                for (int j = 0; j < 8; ++j)
                    acc[i][j] = fmaf(a[i], bb[j], acc[i][j]);
        }
        __syncthreads();
    }

    // Fused epilogue: per-row partial energy over this o-tile
    const int b = m0 / SS;     // all 128 rows of a tile share the same batch (SS % TM == 0)
    float part[8];
    #pragma unroll
    for (int i = 0; i < 8; ++i) part[i] = 0.f;
    #pragma unroll
    for (int j = 0; j < 8; ++j) {
        int o = o0 + tx * 8 + j;
        float va = Va[o];
        float q  = g_qc[b * HH + o];
        #pragma unroll
        for (int i = 0; i < 8; ++i)
            part[i] += va * tanh_acc(acc[i][j] + q);
    }
    // reduce across the 16 tx lanes (xor stays inside each 16-lane half-warp)
    #pragma unroll
    for (int off = 8; off; off >>= 1)
        #pragma unroll
        for (int i = 0; i < 8; ++i)
            part[i] += __shfl_xor_sync(0xffffffffu, part[i], off);
    if (tx == 0) {
        #pragma unroll
        for (int i = 0; i < 8; ++i)
            g_part[ot][m0 + ty * 8 + i] = part[i];
    }
}

// ---------------------------------------------------------------------------
// Kernel 3: sparsemax per batch row. Sort-free: bisection on
//   f(tau) = sum max(z - tau, 0), monotone decreasing, f(tau*)=1,
// then exact refinement tau = (sum_{z>tau} z - 1)/|{z>tau}| (matches the
// reference's sorted-cumsum formula on the identified support).
// Also reduces the NT per-o-tile partials and adds Va_b.
// ---------------------------------------------------------------------------
__global__ void sparsemax_kernel(const float* __restrict__ Va_b,
                                 float* __restrict__ wout) {
    __shared__ float z[SS];
    __shared__ float red[33];
    const int b = blockIdx.x;
    const int tid = threadIdx.x;   // 256 threads
    const float vb = Va_b[0];

    for (int s = tid; s < SS; s += 256) {
        float e = vb;
        #pragma unroll
        for (int t = 0; t < NT; ++t) e += g_part[t][b * SS + s];
        z[s] = e;
    }
    __syncthreads();

    // block max
    float mx = -3.4e38f;
    for (int s = tid; s < SS; s += 256) mx = fmaxf(mx, z[s]);
    #pragma unroll
    for (int off = 16; off; off >>= 1) mx = fmaxf(mx, __shfl_xor_sync(0xffffffffu, mx, off));
    if ((tid & 31) == 0) red[tid >> 5] = mx;
    __syncthreads();
    if (tid == 0) {
        float m = red[0];
        for (int i = 1; i < 8; ++i) m = fmaxf(m, red[i]);
        red[32] = m;
    }
    __syncthreads();
    const float zmax = red[32];
    __syncthreads();

    // bisection: tau* in [zmax-1, zmax]
    float lo = zmax - 1.f, hi = zmax;
    for (int it = 0; it < 48; ++it) {
        float mid = 0.5f * (lo + hi);
        float sum = 0.f;
        for (int s = tid; s < SS; s += 256) sum += fmaxf(z[s] - mid, 0.f);
        #pragma unroll
        for (int off = 16; off; off >>= 1) sum += __shfl_xor_sync(0xffffffffu, sum, off);
        if ((tid & 31) == 0) red[tid >> 5] = sum;
        __syncthreads();
        if (tid == 0) {
            float t = 0.f;
            for (int i = 0; i < 8; ++i) t += red[i];
            red[32] = t;
        }
        __syncthreads();
        float tot = red[32];
        __syncthreads();
        if (tot >= 1.f) lo = mid; else hi = mid;
    }
    float tau = 0.5f * (lo + hi);

    // exact refinement on the identified support (2 passes)
    for (int r = 0; r < 2; ++r) {
        float cnt = 0.f, ssum = 0.f;
        for (int s = tid; s < SS; s += 256) {
            float zv = z[s];
            if (zv > tau) { cnt += 1.f; ssum += zv; }
        }
        #pragma unroll
        for (int off = 16; off; off >>= 1) {
            cnt  += __shfl_xor_sync(0xffffffffu, cnt,  off);
            ssum += __shfl_xor_sync(0xffffffffu, ssum, off);
        }
        if ((tid & 31) == 0) { red[tid >> 5] = cnt; red[8 + (tid >> 5)] = ssum; }
        __syncthreads();
        if (tid == 0) {
            float c = 0.f, s2 = 0.f;
            for (int i = 0; i < 8; ++i) { c += red[i]; s2 += red[8 + i]; }
            red[32] = (s2 - 1.f) / c;
        }
        __syncthreads();
        tau = red[32];
        __syncthreads();
    }

    for (int s = tid; s < SS; s += 256)
        wout[b * SS + s] = fmaxf(z[s] - tau, 0.f);
}

// ---------------------------------------------------------------------------
// Kernel 4: context[b,h] = sum_s w[b,s]*enc[b,s,h]. Exploits sparsemax
// sparsity: the w==0 test is uniform across the block (w broadcast, L1-hit),
// so entire 4KB enc rows are skipped when the weight is zero.
// ---------------------------------------------------------------------------
__global__ void context_kernel(const float* __restrict__ enc,
                               const float* __restrict__ w,
                               float* __restrict__ ctx) {
    const int b = blockIdx.y;
    const int h = blockIdx.x * 256 + threadIdx.x;
    const float* wr = w + b * SS;
    const float* e  = enc + (size_t)b * SS * HH + h;
    float acc = 0.f;
    #pragma unroll 8
    for (int s = 0; s < SS; ++s) {
        float ws = wr[s];
        if (ws != 0.f) acc = fmaf(ws, e[(size_t)s * HH], acc);
    }
    ctx[b * HH + h] = acc;
}

// ---------------------------------------------------------------------------
extern "C" void kernel_launch(void* const* d_in, const int* in_sizes, int n_in,
                              void* d_out, int out_size) {
    const float* enc  = (const float*)d_in[0];   // [B,S,H]
    const float* dec  = (const float*)d_in[1];   // [B,H]
    const float* Wa_w = (const float*)d_in[2];   // [H,H]
    const float* Wa_b = (const float*)d_in[3];   // [H]
    const float* Ua_w = (const float*)d_in[4];   // [H,H]
    const float* Ua_b = (const float*)d_in[5];   // [H]
    const float* Va_w = (const float*)d_in[6];   // [1,H]
    const float* Va_b = (const float*)d_in[7];   // [1]

    float* out = (float*)d_out;
    float* ctx = out;               // context: B*H floats
    float* wts = out + BB * HH;     // attention weights: B*S floats

    qc_kernel<<<(BB * HH) / 8, 256>>>(dec, Wa_w, Wa_b, Ua_b);

    dim3 g(NT, MTOT / TM);          // (8, 512); consecutive CTAs share the A row-tile via L2
    energy_gemm<<<g, 256>>>(enc, Ua_w, Va_w);

    sparsemax_kernel<<<BB, 256>>>(Va_b, wts);

    dim3 gc(HH / 256, BB);
    context_kernel<<<gc, 256>>>(enc, wts, ctx);
}

// round 5
// speedup vs baseline: 2.3512x; 2.3512x over previous
#include <cuda_runtime.h>
#include <cuda_bf16.h>
#include <stdint.h>

#define BB 32
#define SS 2048
#define HH 1024
#define MTOT (BB*SS)
#define NT 8            // 128-wide o-tiles
#define KC 32           // k per stage (bf16)
#define NKT (HH/KC)     // 32
#define SCH 8           // context s-chunks

// smem geometry for the GEMM
#define LDA 40                      // padded row stride (bf16 elems): 80B, conflict-free
#define TILEB (128*LDA*2)           // 10240 B per tile
#define STAGEB (4*TILEB)            // Ah,Al,Bh,Bl
#define OF_VA (2*STAGEB)            // 81920
#define OF_QC (OF_VA+512)
#define OF_PART (OF_QC+512)
#define GEMM_SMEM (OF_PART+1024)    // 83968

// ---------------- device scratch (no allocs allowed) ----------------
__device__ float g_qc[BB*HH];
__device__ float g_part[NT][MTOT];
__device__ float g_cpart[SCH][BB][HH];
__device__ __nv_bfloat16 g_ehi[(size_t)MTOT*HH];   // 128MB
__device__ __nv_bfloat16 g_elo[(size_t)MTOT*HH];   // 128MB
__device__ __nv_bfloat16 g_uhi[HH*HH];
__device__ __nv_bfloat16 g_ulo[HH*HH];

// ---------------- helpers ----------------
__device__ __forceinline__ uint32_t smem_u32(const void* p) {
    uint32_t a;
    asm("{ .reg .u64 t; cvta.to.shared.u64 t, %1; cvt.u32.u64 %0, t; }" : "=r"(a) : "l"(p));
    return a;
}
__device__ __forceinline__ void ldsm4(uint32_t a, uint32_t& r0, uint32_t& r1,
                                      uint32_t& r2, uint32_t& r3) {
    asm volatile("ldmatrix.sync.aligned.m8n8.x4.shared.b16 {%0,%1,%2,%3}, [%4];"
                 : "=r"(r0), "=r"(r1), "=r"(r2), "=r"(r3) : "r"(a));
}
__device__ __forceinline__ void mma16816(float* d, const uint32_t* a, uint32_t b0, uint32_t b1) {
    asm volatile("mma.sync.aligned.m16n8k16.row.col.f32.bf16.bf16.f32 "
                 "{%0,%1,%2,%3}, {%4,%5,%6,%7}, {%8,%9}, {%0,%1,%2,%3};"
                 : "+f"(d[0]), "+f"(d[1]), "+f"(d[2]), "+f"(d[3])
                 : "r"(a[0]), "r"(a[1]), "r"(a[2]), "r"(a[3]), "r"(b0), "r"(b1));
}
// flag-independent tanh: 1 - 2/(1+e^{2x}); exact saturation at +/-inf.
__device__ __forceinline__ float tanh_fast(float x) {
    float e;
    asm("ex2.approx.f32 %0, %1;" : "=f"(e) : "f"(x * 2.8853900817779268f));
    return 1.f - __fdividef(2.f, 1.f + e);
}

// ---------------- kernels 0a/0b: fp32 -> bf16 hi/lo split ----------------
__device__ __forceinline__ void split4(float4 v, uint2& ph, uint2& pl) {
    __nv_bfloat16 h0 = __float2bfloat16(v.x), h1 = __float2bfloat16(v.y);
    __nv_bfloat16 h2 = __float2bfloat16(v.z), h3 = __float2bfloat16(v.w);
    __nv_bfloat16 l0 = __float2bfloat16(v.x - __bfloat162float(h0));
    __nv_bfloat16 l1 = __float2bfloat16(v.y - __bfloat162float(h1));
    __nv_bfloat16 l2 = __float2bfloat16(v.z - __bfloat162float(h2));
    __nv_bfloat16 l3 = __float2bfloat16(v.w - __bfloat162float(h3));
    ph.x = (uint32_t)__bfloat16_as_ushort(h0) | ((uint32_t)__bfloat16_as_ushort(h1) << 16);
    ph.y = (uint32_t)__bfloat16_as_ushort(h2) | ((uint32_t)__bfloat16_as_ushort(h3) << 16);
    pl.x = (uint32_t)__bfloat16_as_ushort(l0) | ((uint32_t)__bfloat16_as_ushort(l1) << 16);
    pl.y = (uint32_t)__bfloat16_as_ushort(l2) | ((uint32_t)__bfloat16_as_ushort(l3) << 16);
}
__global__ void split_enc_kernel(const float* __restrict__ src) {
    int i = blockIdx.x * 256 + threadIdx.x;
    uint2 ph, pl;
    split4(((const float4*)src)[i], ph, pl);
    ((uint2*)g_ehi)[i] = ph;
    ((uint2*)g_elo)[i] = pl;
}
__global__ void split_ua_kernel(const float* __restrict__ src) {
    int i = blockIdx.x * 256 + threadIdx.x;
    uint2 ph, pl;
    split4(((const float4*)src)[i], ph, pl);
    ((uint2*)g_uhi)[i] = ph;
    ((uint2*)g_ulo)[i] = pl;
}

// ---------------- kernel 1: qc[b,o] = dec@Wa^T + Wa_b + Ua_b ----------------
__global__ void qc_kernel(const float* __restrict__ dec,
                          const float* __restrict__ Wa_w,
                          const float* __restrict__ Wa_b,
                          const float* __restrict__ Ua_b) {
    int gw = (blockIdx.x * blockDim.x + threadIdx.x) >> 5;
    int lane = threadIdx.x & 31;
    if (gw >= BB * HH) return;
    int b = gw >> 10;
    int o = gw & (HH - 1);
    const float* dr = dec + b * HH;
    const float* wr = Wa_w + o * HH;
    float s = 0.f;
    #pragma unroll 8
    for (int h = lane; h < HH; h += 32) s = fmaf(dr[h], wr[h], s);
    #pragma unroll
    for (int off = 16; off; off >>= 1) s += __shfl_xor_sync(0xffffffffu, s, off);
    if (lane == 0) g_qc[gw] = s + Wa_b[o] + Ua_b[o];
}

// ---------------- kernel 2: HMMA energy GEMM (bf16x3 split, fp32 acc) -------
// CTA: 128 rows x 128 o. 8 warps (4x2), warp tile 32x64. cp.async double buffer.
// D = Ah*Bh + Ah*Bl + Al*Bh; fused tanh-dot epilogue -> g_part[ot][m].
__device__ __forceinline__ void issue_stage(
        uint32_t sb, int st, int kt, int tid,
        const __nv_bfloat16* sA_hi, const __nv_bfloat16* sA_lo,
        const __nv_bfloat16* sB_hi, const __nv_bfloat16* sB_lo) {
    const __nv_bfloat16* srcs[4] = { sA_hi, sA_lo, sB_hi, sB_lo };
    #pragma unroll
    for (int t = 0; t < 8; ++t) {
        const int arr = t >> 1;                 // compile-time per unrolled t
        int idx = ((t & 1) << 8) + tid;         // 0..511
        int r = idx >> 2, cc = idx & 3;
        const __nv_bfloat16* g = srcs[arr] + (size_t)r * HH + kt * KC + cc * 8;
        uint32_t s = sb + st * STAGEB + arr * TILEB + (uint32_t)(r * LDA + cc * 8) * 2;
        asm volatile("cp.async.cg.shared.global [%0], [%1], 16;" :: "r"(s), "l"(g));
    }
    asm volatile("cp.async.commit_group;" ::: "memory");
}

__global__ __launch_bounds__(256, 2)
void energy_gemm_hmma(const float* __restrict__ Va) {
    extern __shared__ char smem[];
    uint32_t sb = smem_u32(smem);
    const int tid = threadIdx.x, wid = tid >> 5, lane = tid & 31;
    const int ot = blockIdx.x, m0 = blockIdx.y * 128, o0 = ot * 128;
    const int b = m0 >> 11;                 // / SS
    const int wm = wid & 3, wn = wid >> 2;  // warp grid 4x2
    const int tT = lane >> 3, r8 = lane & 7;  // ldmatrix lane mapping

    if (tid < 128) {
        ((float*)(smem + OF_VA))[tid] = Va[o0 + tid];
        ((float*)(smem + OF_QC))[tid] = g_qc[b * HH + o0 + tid];
    }

    const __nv_bfloat16* sAh = g_ehi + (size_t)m0 * HH;
    const __nv_bfloat16* sAl = g_elo + (size_t)m0 * HH;
    const __nv_bfloat16* sBh = g_uhi + (size_t)o0 * HH;
    const __nv_bfloat16* sBl = g_ulo + (size_t)o0 * HH;

    float acc[2][8][4];
    #pragma unroll
    for (int i = 0; i < 2; ++i)
        #pragma unroll
        for (int j = 0; j < 8; ++j)
            #pragma unroll
            for (int k = 0; k < 4; ++k) acc[i][j][k] = 0.f;

    issue_stage(sb, 0, 0, tid, sAh, sAl, sBh, sBl);

    for (int kt = 0; kt < NKT; ++kt) {
        if (kt + 1 < NKT) {
            issue_stage(sb, (kt + 1) & 1, kt + 1, tid, sAh, sAl, sBh, sBl);
            asm volatile("cp.async.wait_group 1;" ::: "memory");
        } else {
            asm volatile("cp.async.wait_group 0;" ::: "memory");
        }
        __syncthreads();
        uint32_t stb = sb + (uint32_t)(kt & 1) * STAGEB;

        #pragma unroll
        for (int kk = 0; kk < 2; ++kk) {   // two k16 halves of KC=32
            // A fragments (hi & lo), 2 m-blocks
            uint32_t ah[2][4], al[2][4];
            #pragma unroll
            for (int mb = 0; mb < 2; ++mb) {
                uint32_t row = wm * 32 + mb * 16 + (tT & 1) * 8 + r8;
                uint32_t col = kk * 16 + (tT >> 1) * 8;
                uint32_t aH = stb + (row * LDA + col) * 2;
                ldsm4(aH, ah[mb][0], ah[mb][1], ah[mb][2], ah[mb][3]);
                ldsm4(aH + TILEB, al[mb][0], al[mb][1], al[mb][2], al[mb][3]);
            }
            #pragma unroll
            for (int q = 0; q < 4; ++q) {  // 16-col N chunk (nblocks 2q, 2q+1)
                uint32_t nrow = wn * 64 + q * 16 + (tT >> 1) * 8 + r8;
                uint32_t ncol = kk * 16 + (tT & 1) * 8;
                uint32_t bA = stb + 2 * TILEB + (nrow * LDA + ncol) * 2;
                uint32_t bh0, bh1, bh2, bh3, bl0, bl1, bl2, bl3;
                ldsm4(bA, bh0, bh1, bh2, bh3);
                ldsm4(bA + TILEB, bl0, bl1, bl2, bl3);
                #pragma unroll
                for (int mb = 0; mb < 2; ++mb) {
                    mma16816(acc[mb][2 * q + 0], ah[mb], bh0, bh1);   // Ah*Bh
                    mma16816(acc[mb][2 * q + 1], ah[mb], bh2, bh3);
                    mma16816(acc[mb][2 * q + 0], ah[mb], bl0, bl1);   // Ah*Bl
                    mma16816(acc[mb][2 * q + 1], ah[mb], bl2, bl3);
                    mma16816(acc[mb][2 * q + 0], al[mb], bh0, bh1);   // Al*Bh
                    mma16816(acc[mb][2 * q + 1], al[mb], bh2, bh3);
                }
            }
        }
        __syncthreads();
    }

    // Fused epilogue: part[m] = sum_o Va[o]*tanh(acc + qc[o])
    const float* sva = (const float*)(smem + OF_VA);
    const float* sqc = (const float*)(smem + OF_QC);
    const int gid = lane >> 2, t4 = lane & 3;
    float pm[4] = {0.f, 0.f, 0.f, 0.f};
    #pragma unroll
    for (int mb = 0; mb < 2; ++mb)
        #pragma unroll
        for (int nb = 0; nb < 8; ++nb) {
            int o = wn * 64 + nb * 8 + t4 * 2;
            float va0 = sva[o], va1 = sva[o + 1];
            float q0 = sqc[o], q1 = sqc[o + 1];
            pm[mb * 2 + 0] += va0 * tanh_fast(acc[mb][nb][0] + q0)
                            + va1 * tanh_fast(acc[mb][nb][1] + q1);
            pm[mb * 2 + 1] += va0 * tanh_fast(acc[mb][nb][2] + q0)
                            + va1 * tanh_fast(acc[mb][nb][3] + q1);
        }
    #pragma unroll
    for (int off = 1; off <= 2; off <<= 1) {
        #pragma unroll
        for (int i = 0; i < 4; ++i) pm[i] += __shfl_xor_sync(0xffffffffu, pm[i], off);
    }
    float* sp = (float*)(smem + OF_PART);
    if (t4 == 0) {
        #pragma unroll
        for (int mb = 0; mb < 2; ++mb) {
            sp[wn * 128 + wm * 32 + mb * 16 + gid]     = pm[mb * 2 + 0];
            sp[wn * 128 + wm * 32 + mb * 16 + 8 + gid] = pm[mb * 2 + 1];
        }
    }
    __syncthreads();
    if (tid < 128) g_part[ot][m0 + tid] = sp[tid] + sp[128 + tid];
}

// ---------------- kernel 3: sparsemax (sort-free, exact) ----------------
__global__ void sparsemax_kernel(const float* __restrict__ Va_b,
                                 float* __restrict__ wout) {
    __shared__ float z[SS];
    __shared__ float red[33];
    const int b = blockIdx.x;
    const int tid = threadIdx.x;
    const float vb = Va_b[0];

    for (int s = tid; s < SS; s += 256) {
        float e = vb;
        #pragma unroll
        for (int t = 0; t < NT; ++t) e += g_part[t][b * SS + s];
        z[s] = e;
    }
    __syncthreads();

    float mx = -3.4e38f;
    for (int s = tid; s < SS; s += 256) mx = fmaxf(mx, z[s]);
    #pragma unroll
    for (int off = 16; off; off >>= 1) mx = fmaxf(mx, __shfl_xor_sync(0xffffffffu, mx, off));
    if ((tid & 31) == 0) red[tid >> 5] = mx;
    __syncthreads();
    if (tid == 0) {
        float m = red[0];
        for (int i = 1; i < 8; ++i) m = fmaxf(m, red[i]);
        red[32] = m;
    }
    __syncthreads();
    const float zmax = red[32];
    __syncthreads();

    float lo = zmax - 1.f, hi = zmax;
    for (int it = 0; it < 48; ++it) {
        float mid = 0.5f * (lo + hi);
        float sum = 0.f;
        for (int s = tid; s < SS; s += 256) sum += fmaxf(z[s] - mid, 0.f);
        #pragma unroll
        for (int off = 16; off; off >>= 1) sum += __shfl_xor_sync(0xffffffffu, sum, off);
        if ((tid & 31) == 0) red[tid >> 5] = sum;
        __syncthreads();
        if (tid == 0) {
            float t = 0.f;
            for (int i = 0; i < 8; ++i) t += red[i];
            red[32] = t;
        }
        __syncthreads();
        float tot = red[32];
        __syncthreads();
        if (tot >= 1.f) lo = mid; else hi = mid;
    }
    float tau = 0.5f * (lo + hi);

    for (int r2 = 0; r2 < 2; ++r2) {
        float cnt = 0.f, ssum = 0.f;
        for (int s = tid; s < SS; s += 256) {
            float zv = z[s];
            if (zv > tau) { cnt += 1.f; ssum += zv; }
        }
        #pragma unroll
        for (int off = 16; off; off >>= 1) {
            cnt  += __shfl_xor_sync(0xffffffffu, cnt,  off);
            ssum += __shfl_xor_sync(0xffffffffu, ssum, off);
        }
        if ((tid & 31) == 0) { red[tid >> 5] = cnt; red[8 + (tid >> 5)] = ssum; }
        __syncthreads();
        if (tid == 0) {
            float c = 0.f, s2 = 0.f;
            for (int i = 0; i < 8; ++i) { c += red[i]; s2 += red[8 + i]; }
            red[32] = (s2 - 1.f) / c;
        }
        __syncthreads();
        tau = red[32];
        __syncthreads();
    }

    for (int s = tid; s < SS; s += 256)
        wout[b * SS + s] = fmaxf(z[s] - tau, 0.f);
}

// ---------------- kernel 4: context (S-chunked, sparse skip) ----------------
__global__ void context_part(const float* __restrict__ enc,
                             const float* __restrict__ w) {
    const int b = blockIdx.y, zc = blockIdx.z;
    const int h = blockIdx.x * 256 + threadIdx.x;
    const int SC = SS / SCH;
    const float* wr = w + b * SS + zc * SC;
    const float* e = enc + (size_t)b * SS * HH + (size_t)zc * SC * HH + h;
    float acc = 0.f;
    #pragma unroll 4
    for (int s = 0; s < SC; ++s) {
        float ws = wr[s];
        if (ws != 0.f) acc = fmaf(ws, e[(size_t)s * HH], acc);
    }
    g_cpart[zc][b][h] = acc;
}
__global__ void context_reduce(float* __restrict__ ctx) {
    int i = blockIdx.x * 256 + threadIdx.x;
    int b = i >> 10, h = i & 1023;
    float a = 0.f;
    #pragma unroll
    for (int zc = 0; zc < SCH; ++zc) a += g_cpart[zc][b][h];
    ctx[i] = a;
}

// ---------------------------------------------------------------------------
extern "C" void kernel_launch(void* const* d_in, const int* in_sizes, int n_in,
                              void* d_out, int out_size) {
    const float* enc  = (const float*)d_in[0];
    const float* dec  = (const float*)d_in[1];
    const float* Wa_w = (const float*)d_in[2];
    const float* Wa_b = (const float*)d_in[3];
    const float* Ua_w = (const float*)d_in[4];
    const float* Ua_b = (const float*)d_in[5];
    const float* Va_w = (const float*)d_in[6];
    const float* Va_b = (const float*)d_in[7];

    float* out = (float*)d_out;
    float* ctx = out;               // context [B,1,H]
    float* wts = out + BB * HH;     // attention weights [B,S]

    cudaFuncSetAttribute(energy_gemm_hmma,
                         cudaFuncAttributeMaxDynamicSharedMemorySize, GEMM_SMEM);

    split_enc_kernel<<<(MTOT * (HH / 4)) / 256, 256>>>(enc);
    split_ua_kernel<<<(HH * (HH / 4)) / 256, 256>>>(Ua_w);
    qc_kernel<<<(BB * HH) / 8, 256>>>(dec, Wa_w, Wa_b, Ua_b);

    dim3 g(NT, MTOT / 128);   // (8, 512); o-tile fastest -> A panel L2 reuse
    energy_gemm_hmma<<<g, 256, GEMM_SMEM>>>(Va_w);

    sparsemax_kernel<<<BB, 256>>>(Va_b, wts);

    dim3 gc(HH / 256, BB, SCH);
    context_part<<<gc, 256>>>(enc, wts);
    context_reduce<<<(BB * HH) / 256, 256>>>(ctx);
}

// round 6
// speedup vs baseline: 2.7287x; 1.1605x over previous
#include <cuda_runtime.h>
#include <cuda_bf16.h>
#include <stdint.h>

#define BB 32
#define SS 2048
#define HH 1024
#define MTOT (BB*SS)
#define NT 8            // 128-wide o-tiles
#define KC 32           // k per stage (bf16)
#define NKT (HH/KC)     // 32
#define SCH 8           // context s-chunks

// smem geometry: unpadded 64B rows + XOR swizzle, 3-stage ring
#define TILEB 8192                  // 128 rows x 64B
#define STAGEB (4*TILEB)            // Ah,Al,Bh,Bl = 32KB
#define NSTG 3
#define OF_VA (NSTG*STAGEB)         // 98304
#define OF_QC (OF_VA+512)
#define OF_PART (OF_QC+512)
#define GEMM_SMEM (OF_PART+1024)    // 100352

#define SWZ(o) ((o) ^ (((o) >> 3) & 0x70))

// ---------------- device scratch (no allocs allowed) ----------------
__device__ float g_qc[BB*HH];
__device__ float g_part[NT][MTOT];
__device__ float g_cpart[SCH][BB][HH];
__device__ __nv_bfloat16 g_ehi[(size_t)MTOT*HH];   // 128MB
__device__ __nv_bfloat16 g_elo[(size_t)MTOT*HH];   // 128MB
__device__ __nv_bfloat16 g_uhi[HH*HH];
__device__ __nv_bfloat16 g_ulo[HH*HH];

// ---------------- helpers ----------------
__device__ __forceinline__ uint32_t smem_u32(const void* p) {
    uint32_t a;
    asm("{ .reg .u64 t; cvta.to.shared.u64 t, %1; cvt.u32.u64 %0, t; }" : "=r"(a) : "l"(p));
    return a;
}
__device__ __forceinline__ void ldsm4(uint32_t a, uint32_t& r0, uint32_t& r1,
                                      uint32_t& r2, uint32_t& r3) {
    asm volatile("ldmatrix.sync.aligned.m8n8.x4.shared.b16 {%0,%1,%2,%3}, [%4];"
                 : "=r"(r0), "=r"(r1), "=r"(r2), "=r"(r3) : "r"(a));
}
__device__ __forceinline__ void mma16816(float* d, const uint32_t* a, uint32_t b0, uint32_t b1) {
    asm volatile("mma.sync.aligned.m16n8k16.row.col.f32.bf16.bf16.f32 "
                 "{%0,%1,%2,%3}, {%4,%5,%6,%7}, {%8,%9}, {%0,%1,%2,%3};"
                 : "+f"(d[0]), "+f"(d[1]), "+f"(d[2]), "+f"(d[3])
                 : "r"(a[0]), "r"(a[1]), "r"(a[2]), "r"(a[3]), "r"(b0), "r"(b1));
}
// flag-independent tanh: 1 - 2/(1+e^{2x}); exact saturation at +/-inf.
__device__ __forceinline__ float tanh_fast(float x) {
    float e;
    asm("ex2.approx.f32 %0, %1;" : "=f"(e) : "f"(x * 2.8853900817779268f));
    return 1.f - __fdividef(2.f, 1.f + e);
}

// ---------------- kernels 0a/0b: fp32 -> bf16 hi/lo split ----------------
__device__ __forceinline__ void split4(float4 v, uint2& ph, uint2& pl) {
    __nv_bfloat16 h0 = __float2bfloat16(v.x), h1 = __float2bfloat16(v.y);
    __nv_bfloat16 h2 = __float2bfloat16(v.z), h3 = __float2bfloat16(v.w);
    __nv_bfloat16 l0 = __float2bfloat16(v.x - __bfloat162float(h0));
    __nv_bfloat16 l1 = __float2bfloat16(v.y - __bfloat162float(h1));
    __nv_bfloat16 l2 = __float2bfloat16(v.z - __bfloat162float(h2));
    __nv_bfloat16 l3 = __float2bfloat16(v.w - __bfloat162float(h3));
    ph.x = (uint32_t)__bfloat16_as_ushort(h0) | ((uint32_t)__bfloat16_as_ushort(h1) << 16);
    ph.y = (uint32_t)__bfloat16_as_ushort(h2) | ((uint32_t)__bfloat16_as_ushort(h3) << 16);
    pl.x = (uint32_t)__bfloat16_as_ushort(l0) | ((uint32_t)__bfloat16_as_ushort(l1) << 16);
    pl.y = (uint32_t)__bfloat16_as_ushort(l2) | ((uint32_t)__bfloat16_as_ushort(l3) << 16);
}
__global__ void split_enc_kernel(const float* __restrict__ src) {
    int i = blockIdx.x * 256 + threadIdx.x;
    uint2 ph, pl;
    split4(((const float4*)src)[i], ph, pl);
    ((uint2*)g_ehi)[i] = ph;
    ((uint2*)g_elo)[i] = pl;
}
__global__ void split_ua_kernel(const float* __restrict__ src) {
    int i = blockIdx.x * 256 + threadIdx.x;
    uint2 ph, pl;
    split4(((const float4*)src)[i], ph, pl);
    ((uint2*)g_uhi)[i] = ph;
    ((uint2*)g_ulo)[i] = pl;
}

// ---------------- kernel 1: qc[b,o] = dec@Wa^T + Wa_b + Ua_b ----------------
__global__ void qc_kernel(const float* __restrict__ dec,
                          const float* __restrict__ Wa_w,
                          const float* __restrict__ Wa_b,
                          const float* __restrict__ Ua_b) {
    int gw = (blockIdx.x * blockDim.x + threadIdx.x) >> 5;
    int lane = threadIdx.x & 31;
    if (gw >= BB * HH) return;
    int b = gw >> 10;
    int o = gw & (HH - 1);
    const float* dr = dec + b * HH;
    const float* wr = Wa_w + o * HH;
    float s = 0.f;
    #pragma unroll 8
    for (int h = lane; h < HH; h += 32) s = fmaf(dr[h], wr[h], s);
    #pragma unroll
    for (int off = 16; off; off >>= 1) s += __shfl_xor_sync(0xffffffffu, s, off);
    if (lane == 0) g_qc[gw] = s + Wa_b[o] + Ua_b[o];
}

// ---------------- kernel 2: HMMA energy GEMM (bf16x3 split, fp32 acc) -------
// CTA: 128x128, 8 warps (4x2), warp tile 32x64. 3-stage cp.async ring,
// ONE __syncthreads per stage. D = Ah*Bh + Ah*Bl + Al*Bh; fused tanh-dot.
__device__ __forceinline__ void issue_stage(
        uint32_t sb, int st, int kt, int tid,
        const __nv_bfloat16* A_hi, const __nv_bfloat16* A_lo,
        const __nv_bfloat16* B_hi, const __nv_bfloat16* B_lo) {
    const __nv_bfloat16* srcs[4] = { A_hi, A_lo, B_hi, B_lo };
    #pragma unroll
    for (int t = 0; t < 8; ++t) {
        const int arr = t >> 1;                 // compile-time per unrolled t
        int idx = ((t & 1) << 8) + tid;         // 0..511 per tile
        int r = idx >> 2, c = idx & 3;
        const __nv_bfloat16* g = srcs[arr] + (size_t)r * HH + kt * KC + c * 8;
        uint32_t byte = (uint32_t)(r * 64 + c * 16);
        uint32_t s = sb + st * STAGEB + arr * TILEB + SWZ(byte);
        asm volatile("cp.async.cg.shared.global [%0], [%1], 16;" :: "r"(s), "l"(g));
    }
    asm volatile("cp.async.commit_group;" ::: "memory");
}

__global__ __launch_bounds__(256, 2)
void energy_gemm_hmma(const float* __restrict__ Va) {
    extern __shared__ __align__(1024) char smem[];
    uint32_t sb = smem_u32(smem);
    const int tid = threadIdx.x, wid = tid >> 5, lane = tid & 31;
    const int ot = blockIdx.x, m0 = blockIdx.y * 128, o0 = ot * 128;
    const int b = m0 >> 11;                 // / SS
    const int wm = wid & 3, wn = wid >> 2;  // warp grid 4x2
    const int tT = lane >> 3, r8 = lane & 7;

    if (tid < 128) {
        ((float*)(smem + OF_VA))[tid] = Va[o0 + tid];
        ((float*)(smem + OF_QC))[tid] = g_qc[b * HH + o0 + tid];
    }

    const __nv_bfloat16* sAh = g_ehi + (size_t)m0 * HH;
    const __nv_bfloat16* sAl = g_elo + (size_t)m0 * HH;
    const __nv_bfloat16* sBh = g_uhi + (size_t)o0 * HH;
    const __nv_bfloat16* sBl = g_ulo + (size_t)o0 * HH;

    float acc[2][8][4];
    #pragma unroll
    for (int i = 0; i < 2; ++i)
        #pragma unroll
        for (int j = 0; j < 8; ++j)
            #pragma unroll
            for (int k = 0; k < 4; ++k) acc[i][j][k] = 0.f;

    issue_stage(sb, 0, 0, tid, sAh, sAl, sBh, sBl);
    issue_stage(sb, 1, 1, tid, sAh, sAl, sBh, sBl);

    for (int kt = 0; kt < NKT; ++kt) {
        // pending groups here: {kt, kt+1}; wait 1 -> stage kt complete (own copies)
        asm volatile("cp.async.wait_group 1;" ::: "memory");
        // one barrier: publishes stage kt to all threads AND releases buffer
        // (kt-1)%3 == (kt+2)%3 (all warps finished compute(kt-1) before this).
        __syncthreads();
        if (kt + 2 < NKT)
            issue_stage(sb, (kt + 2) % NSTG, kt + 2, tid, sAh, sAl, sBh, sBl);
        else
            asm volatile("cp.async.commit_group;" ::: "memory");  // keep group math exact

        uint32_t stb = sb + (uint32_t)(kt % NSTG) * STAGEB;

        #pragma unroll
        for (int kk = 0; kk < 2; ++kk) {   // two k16 halves of KC=32
            uint32_t ah[2][4], al[2][4];
            #pragma unroll
            for (int mb = 0; mb < 2; ++mb) {
                uint32_t row  = wm * 32 + mb * 16 + (tT & 1) * 8 + r8;
                uint32_t byte = row * 64 + (kk * 16 + (tT >> 1) * 8) * 2;
                ldsm4(stb + SWZ(byte), ah[mb][0], ah[mb][1], ah[mb][2], ah[mb][3]);
                ldsm4(stb + TILEB + SWZ(byte), al[mb][0], al[mb][1], al[mb][2], al[mb][3]);
            }
            // software-pipelined B fragments over q
            uint32_t bh[2][4], bl[2][4];
            auto loadB = [&](int q, uint32_t* BH, uint32_t* BL) {
                uint32_t nrow = wn * 64 + q * 16 + (tT >> 1) * 8 + r8;
                uint32_t byte = nrow * 64 + (kk * 16 + (tT & 1) * 8) * 2;
                ldsm4(stb + 2 * TILEB + SWZ(byte), BH[0], BH[1], BH[2], BH[3]);
                ldsm4(stb + 3 * TILEB + SWZ(byte), BL[0], BL[1], BL[2], BL[3]);
            };
            loadB(0, bh[0], bl[0]);
            #pragma unroll
            for (int q = 0; q < 4; ++q) {
                if (q < 3) loadB(q + 1, bh[(q + 1) & 1], bl[(q + 1) & 1]);
                const uint32_t* BH = bh[q & 1];
                const uint32_t* BL = bl[q & 1];
                #pragma unroll
                for (int mb = 0; mb < 2; ++mb) {
                    mma16816(acc[mb][2 * q + 0], ah[mb], BH[0], BH[1]);   // Ah*Bh
                    mma16816(acc[mb][2 * q + 1], ah[mb], BH[2], BH[3]);
                    mma16816(acc[mb][2 * q + 0], ah[mb], BL[0], BL[1]);   // Ah*Bl
                    mma16816(acc[mb][2 * q + 1], ah[mb], BL[2], BL[3]);
                    mma16816(acc[mb][2 * q + 0], al[mb], BH[0], BH[1]);   // Al*Bh
                    mma16816(acc[mb][2 * q + 1], al[mb], BH[2], BH[3]);
                }
            }
        }
    }

    // Fused epilogue: part[m] = sum_o Va[o]*tanh(acc + qc[o])
    const float* sva = (const float*)(smem + OF_VA);
    const float* sqc = (const float*)(smem + OF_QC);
    const int gid = lane >> 2, t4 = lane & 3;
    float pm[4] = {0.f, 0.f, 0.f, 0.f};
    #pragma unroll
    for (int mb = 0; mb < 2; ++mb)
        #pragma unroll
        for (int nb = 0; nb < 8; ++nb) {
            int o = wn * 64 + nb * 8 + t4 * 2;
            float va0 = sva[o], va1 = sva[o + 1];
            float q0 = sqc[o], q1 = sqc[o + 1];
            pm[mb * 2 + 0] += va0 * tanh_fast(acc[mb][nb][0] + q0)
                            + va1 * tanh_fast(acc[mb][nb][1] + q1);
            pm[mb * 2 + 1] += va0 * tanh_fast(acc[mb][nb][2] + q0)
                            + va1 * tanh_fast(acc[mb][nb][3] + q1);
        }
    #pragma unroll
    for (int off = 1; off <= 2; off <<= 1) {
        #pragma unroll
        for (int i = 0; i < 4; ++i) pm[i] += __shfl_xor_sync(0xffffffffu, pm[i], off);
    }
    float* sp = (float*)(smem + OF_PART);
    __syncthreads();   // all compute done before reusing smem region semantics
    if (t4 == 0) {
        #pragma unroll
        for (int mb = 0; mb < 2; ++mb) {
            sp[wn * 128 + wm * 32 + mb * 16 + gid]     = pm[mb * 2 + 0];
            sp[wn * 128 + wm * 32 + mb * 16 + 8 + gid] = pm[mb * 2 + 1];
        }
    }
    __syncthreads();
    if (tid < 128) g_part[ot][m0 + tid] = sp[tid] + sp[128 + tid];
}

// ---------------- kernel 3: sparsemax (sort-free, exact) ----------------
__global__ void sparsemax_kernel(const float* __restrict__ Va_b,
                                 float* __restrict__ wout) {
    __shared__ float z[SS];
    __shared__ float red[33];
    const int b = blockIdx.x;
    const int tid = threadIdx.x;
    const float vb = Va_b[0];

    for (int s = tid; s < SS; s += 256) {
        float e = vb;
        #pragma unroll
        for (int t = 0; t < NT; ++t) e += g_part[t][b * SS + s];
        z[s] = e;
    }
    __syncthreads();

    float mx = -3.4e38f;
    for (int s = tid; s < SS; s += 256) mx = fmaxf(mx, z[s]);
    #pragma unroll
    for (int off = 16; off; off >>= 1) mx = fmaxf(mx, __shfl_xor_sync(0xffffffffu, mx, off));
    if ((tid & 31) == 0) red[tid >> 5] = mx;
    __syncthreads();
    if (tid == 0) {
        float m = red[0];
        for (int i = 1; i < 8; ++i) m = fmaxf(m, red[i]);
        red[32] = m;
    }
    __syncthreads();
    const float zmax = red[32];
    __syncthreads();

    float lo = zmax - 1.f, hi = zmax;
    for (int it = 0; it < 32; ++it) {
        float mid = 0.5f * (lo + hi);
        float sum = 0.f;
        for (int s = tid; s < SS; s += 256) sum += fmaxf(z[s] - mid, 0.f);
        #pragma unroll
        for (int off = 16; off; off >>= 1) sum += __shfl_xor_sync(0xffffffffu, sum, off);
        if ((tid & 31) == 0) red[tid >> 5] = sum;
        __syncthreads();
        if (tid == 0) {
            float t = 0.f;
            for (int i = 0; i < 8; ++i) t += red[i];
            red[32] = t;
        }
        __syncthreads();
        float tot = red[32];
        __syncthreads();
        if (tot >= 1.f) lo = mid; else hi = mid;
    }
    float tau = 0.5f * (lo + hi);

    for (int r2 = 0; r2 < 2; ++r2) {
        float cnt = 0.f, ssum = 0.f;
        for (int s = tid; s < SS; s += 256) {
            float zv = z[s];
            if (zv > tau) { cnt += 1.f; ssum += zv; }
        }
        #pragma unroll
        for (int off = 16; off; off >>= 1) {
            cnt  += __shfl_xor_sync(0xffffffffu, cnt,  off);
            ssum += __shfl_xor_sync(0xffffffffu, ssum, off);
        }
        if ((tid & 31) == 0) { red[tid >> 5] = cnt; red[8 + (tid >> 5)] = ssum; }
        __syncthreads();
        if (tid == 0) {
            float c = 0.f, s2 = 0.f;
            for (int i = 0; i < 8; ++i) { c += red[i]; s2 += red[8 + i]; }
            red[32] = (s2 - 1.f) / c;
        }
        __syncthreads();
        tau = red[32];
        __syncthreads();
    }

    for (int s = tid; s < SS; s += 256)
        wout[b * SS + s] = fmaxf(z[s] - tau, 0.f);
}

// ---------------- kernel 4: context (S-chunked, sparse skip) ----------------
__global__ void context_part(const float* __restrict__ enc,
                             const float* __restrict__ w) {
    const int b = blockIdx.y, zc = blockIdx.z;
    const int h = blockIdx.x * 256 + threadIdx.x;
    const int SC = SS / SCH;
    const float* wr = w + b * SS + zc * SC;
    const float* e = enc + (size_t)b * SS * HH + (size_t)zc * SC * HH + h;
    float acc = 0.f;
    #pragma unroll 4
    for (int s = 0; s < SC; ++s) {
        float ws = wr[s];
        if (ws != 0.f) acc = fmaf(ws, e[(size_t)s * HH], acc);
    }
    g_cpart[zc][b][h] = acc;
}
__global__ void context_reduce(float* __restrict__ ctx) {
    int i = blockIdx.x * 256 + threadIdx.x;
    int b = i >> 10, h = i & 1023;
    float a = 0.f;
    #pragma unroll
    for (int zc = 0; zc < SCH; ++zc) a += g_cpart[zc][b][h];
    ctx[i] = a;
}

// ---------------------------------------------------------------------------
extern "C" void kernel_launch(void* const* d_in, const int* in_sizes, int n_in,
                              void* d_out, int out_size) {
    const float* enc  = (const float*)d_in[0];
    const float* dec  = (const float*)d_in[1];
    const float* Wa_w = (const float*)d_in[2];
    const float* Wa_b = (const float*)d_in[3];
    const float* Ua_w = (const float*)d_in[4];
    const float* Ua_b = (const float*)d_in[5];
    const float* Va_w = (const float*)d_in[6];
    const float* Va_b = (const float*)d_in[7];

    float* out = (float*)d_out;
    float* ctx = out;               // context [B,1,H]
    float* wts = out + BB * HH;     // attention weights [B,S]

    cudaFuncSetAttribute(energy_gemm_hmma,
                         cudaFuncAttributeMaxDynamicSharedMemorySize, GEMM_SMEM);

    split_enc_kernel<<<(MTOT * (HH / 4)) / 256, 256>>>(enc);
    split_ua_kernel<<<(HH * (HH / 4)) / 256, 256>>>(Ua_w);
    qc_kernel<<<(BB * HH) / 8, 256>>>(dec, Wa_w, Wa_b, Ua_b);

    dim3 g(NT, MTOT / 128);   // (8, 512); o-tile fastest -> A panel L2 reuse
    energy_gemm_hmma<<<g, 256, GEMM_SMEM>>>(Va_w);

    sparsemax_kernel<<<BB, 256>>>(Va_b, wts);

    dim3 gc(HH / 256, BB, SCH);
    context_part<<<gc, 256>>>(enc, wts);
    context_reduce<<<(BB * HH) / 256, 256>>>(ctx);
}